// round 6
// baseline (speedup 1.0000x reference)
#include <cuda_runtime.h>

// Fused 3-phase LSTM (cent H=32 x100, enc H=64 x20, dec H=96 x30).
// R5 = R1's exact inner loops + new sync topology:
//  - 2 independent 256-thread groups, each owning 32 batch columns end-to-end,
//    synced ONLY by group-local named barriers -> group A's MUFU activation
//    burst overlaps group B's FFMA2 stream on every SMSP.
//  - anti-phase schedule: group0 cent->enc, group1 enc->cent.
//  - double-buffered h/x: ONE barrier per recurrence step.

#define TPB  512
#define BT   64
#define GBT  32      // batch columns per group

typedef unsigned long long ull;

// ---------------- packed f32x2 helpers ----------------
__device__ __forceinline__ ull pk2(float lo, float hi) {
    ull r; asm("mov.b64 %0, {%1, %2};" : "=l"(r) : "f"(lo), "f"(hi)); return r;
}
__device__ __forceinline__ ull dup2(float x) {
    ull r; asm("mov.b64 %0, {%1, %1};" : "=l"(r) : "f"(x)); return r;
}
__device__ __forceinline__ ull fma2(ull a, ull b, ull c) {
    ull d; asm("fma.rn.f32x2 %0, %1, %2, %3;" : "=l"(d) : "l"(a), "l"(b), "l"(c)); return d;
}
__device__ __forceinline__ float2 upk(ull a) {
    float lo, hi; asm("mov.b64 {%0, %1}, %2;" : "=f"(lo), "=f"(hi) : "l"(a));
    return make_float2(lo, hi);
}

// ---------------- fast activations (ex2-based, proven 7e-7 rel err) ----------------
__device__ __forceinline__ float fex2(float x){ float r; asm("ex2.approx.f32 %0, %1;" : "=f"(r) : "f"(x)); return r; }
__device__ __forceinline__ float frcp(float x){ float r; asm("rcp.approx.f32 %0, %1;" : "=f"(r) : "f"(x)); return r; }
__device__ __forceinline__ float sigm(float x){
    return frcp(1.0f + fex2(-1.4426950408889634f * x));
}
__device__ __forceinline__ float tanh_(float x){
    return fmaf(2.0f, sigm(2.0f * x), -1.0f);
}

// ---------------- group-local named barrier (256 threads) ----------------
__device__ __forceinline__ void gbar(int g) {
    asm volatile("bar.sync %0, %1;" :: "r"(g + 1), "r"(256) : "memory");
}

// ---------------- SMEM layout (float offsets) ----------------
// Phases: WS_C + WS_E live together; WS_D (36864) is staged AFTER both phases
// finish and clobbers [0,36864) including Cs (c is read into regs first).
#define WS_D_OFF  0        // decoder weights [0,36864)
#define WS_C_OFF  0        // cent weights   [0,4096)
#define WS_E_OFF  4096     // enc weights    [4096,20480)
#define CS_OFF    20480    // c staging [96][64] = 6144 -> [20480,26624)
#define HS_OFF    36864    // h state: 2 buffers x [96][64] = 2*6144
#define XS_OFF    49152    // dup'd x: 2 buffers x 128 ull = 512 floats
#define BPKC_OFF  49664    // cent bias:  64 ull
#define IPKC_OFF  49792    // cent Wih:  128 ull
#define BPKE_OFF  50048    // enc bias:  128 ull
#define IPKE_OFF  50304    // enc Wih:   256 ull
#define BPKD_OFF  50816    // dec bias:  192 ull
#define WEMB_OFF  51200    // 96 float2
#define BEMB_OFF  51392
#define SMEM_FLOATS 51396
#define SMEM_BYTES  (SMEM_FLOATS * 4)

// ---------------- weight/bias staging (CTA-wide) ----------------
template<int H>
__device__ __forceinline__ void load_W(float* __restrict__ Ws,
                                       const float* __restrict__ Whh,
                                       const float* __restrict__ Wih, int tid)
{
    constexpr int total = 4 * H * H;
    for (int s = tid; s < total; s += TPB) {
        int row = s / H;
        int k   = s - row * H;
        int g   = row / H;
        int j   = row - g * H;
        float v = Whh[s];
        if (Wih) v += Wih[s];
        Ws[k * (4 * H) + j * 4 + g] = v;
    }
}

template<int H>
__device__ __forceinline__ void load_bias(ull* __restrict__ Bpk,
                                          const float* __restrict__ bih,
                                          const float* __restrict__ bhh, int tid)
{
    for (int j = tid; j < H; j += TPB) {
        Bpk[j * 2 + 0] = pk2(bih[j] + bhh[j],             bih[H + j] + bhh[H + j]);
        Bpk[j * 2 + 1] = pk2(bih[2*H + j] + bhh[2*H + j], bih[3*H + j] + bhh[3*H + j]);
    }
}

template<int H>
__device__ __forceinline__ void load_ih(ull* __restrict__ Ipk,
                                        const float* __restrict__ Wih, int tid)
{
    for (int t = tid; t < 2 * H; t += TPB) {
        int j = t >> 1, inp = t & 1;
        Ipk[(j * 2 + inp) * 2 + 0] = pk2(Wih[(0*H + j) * 2 + inp], Wih[(1*H + j) * 2 + inp]);
        Ipk[(j * 2 + inp) * 2 + 1] = pk2(Wih[(2*H + j) * 2 + inp], Wih[(3*H + j) * 2 + inp]);
    }
}

// ---------------- gate matmul: gates += h @ W^T (R1's exact loop) ----------------
template<int H, int NH, int NB>
__device__ __forceinline__ void gates_mm(const float* __restrict__ Ws,
                                         const float* __restrict__ hbase, // Hc+HOFF*BT+bcol
                                         int j0,
                                         ull (&aif)[NH][NB], ull (&ago)[NH][NB])
{
    const float* wb = Ws + j0 * 4;
    #pragma unroll 4
    for (int k = 0; k < H; k++) {
        ull hp[NB];
        if constexpr (NB == 4) {
            float4 hv = *(const float4*)(hbase + k * BT);
            hp[0] = dup2(hv.x); hp[1] = dup2(hv.y); hp[2] = dup2(hv.z); hp[3] = dup2(hv.w);
        } else {
            float2 hv = *(const float2*)(hbase + k * BT);
            hp[0] = dup2(hv.x); hp[1] = dup2(hv.y);
        }
        #pragma unroll
        for (int i = 0; i < NH; i++) {
            ulonglong2 w = *(const ulonglong2*)(wb + k * (4 * H) + i * 4);
            #pragma unroll
            for (int b = 0; b < NB; b++) {
                aif[i][b] = fma2(w.x, hp[b], aif[i][b]);
                ago[i][b] = fma2(w.y, hp[b], ago[i][b]);
            }
        }
    }
}

// ---------------- activations + h store ----------------
template<int NH, int NB>
__device__ __forceinline__ void act_update(ull (&aif)[NH][NB], ull (&ago)[NH][NB],
                                           float (&cr)[NH][NB],
                                           float* __restrict__ Hw) // Hn+(HOFF+j0)*BT+bcol
{
    #pragma unroll
    for (int i = 0; i < NH; i++) {
        float hn[NB];
        #pragma unroll
        for (int b = 0; b < NB; b++) {
            float2 sif = upk(aif[i][b]);
            float2 sgo = upk(ago[i][b]);
            float ig = sigm(sif.x);
            float fg = sigm(sif.y);
            float gg = tanh_(sgo.x);
            float og = sigm(sgo.y);
            float cn = fmaf(fg, cr[i][b], ig * gg);
            cr[i][b] = cn;
            hn[b] = og * tanh_(cn);
        }
        if constexpr (NB == 4)
            *(float4*)(Hw + i * BT) = make_float4(hn[0], hn[1], hn[2], hn[3]);
        else
            *(float2*)(Hw + i * BT) = make_float2(hn[0], hn[1]);
    }
}

// ---------------- one input-driven LSTM phase, group-local ----------------
template<int H, int NH, int NB, int HOFF, int T>
__device__ __forceinline__ void lstm_phase(float* __restrict__ S,
                                           const float* __restrict__ xsrc, int xstride,
                                           int B, int bbase, int g, int tid_g,
                                           int wsOff, int bpkOff, int ipkOff)
{
    constexpr int BG = GBT / NB;
    static_assert((H / NH) * BG == 256, "group thread map");
    int hg = tid_g / BG, bg = tid_g % BG;
    int j0 = hg * NH, bcol = g * GBT + bg * NB;

    float* Ws = S + wsOff;
    float* Cs = S + CS_OFF;
    float* H0 = S + HS_OFF;  float* H1 = H0 + 6144;
    ull*   X0 = (ull*)(S + XS_OFF); ull* X1 = X0 + 128;
    ull*   Bpk = (ull*)(S + bpkOff);
    ull*   Ipk = (ull*)(S + ipkOff);

    float cr[NH][NB];
    #pragma unroll
    for (int i = 0; i < NH; i++)
        #pragma unroll
        for (int b = 0; b < NB; b++) cr[i][b] = 0.0f;

    ull bif[NH], bgo[NH], wif0[NH], wif1[NH], wgo0[NH], wgo1[NH];
    #pragma unroll
    for (int i = 0; i < NH; i++) {
        bif[i]  = Bpk[(j0 + i) * 2 + 0];
        bgo[i]  = Bpk[(j0 + i) * 2 + 1];
        wif0[i] = Ipk[((j0 + i) * 2 + 0) * 2 + 0];
        wgo0[i] = Ipk[((j0 + i) * 2 + 0) * 2 + 1];
        wif1[i] = Ipk[((j0 + i) * 2 + 1) * 2 + 0];
        wgo1[i] = Ipk[((j0 + i) * 2 + 1) * 2 + 1];
    }

    // initial x stage (group-local; 32 stager threads)
    bool stager = (tid_g < GBT);
    int  scol = g * GBT + tid_g;
    int  bb = bbase + scol; if (bb >= B) bb = B - 1;
    if (stager) {
        float2 x = *(const float2*)&xsrc[(size_t)bb * xstride];
        X0[2 * scol + 0] = pk2(x.x, x.x);
        X0[2 * scol + 1] = pk2(x.y, x.y);
    }
    gbar(g);

    float* Hc = H0; float* Hn = H1;
    ull*   Xc = X0; ull*   Xn = X1;

    for (int t = 0; t < T; t++) {
        float2 xnv;
        bool st = stager && (t + 1 < T);
        if (st)   // prefetch next x early; LDG hides under gates_mm
            xnv = *(const float2*)&xsrc[(size_t)bb * xstride + (size_t)(t + 1) * 2];

        ull aif[NH][NB], ago[NH][NB];
        #pragma unroll
        for (int b = 0; b < NB; b++) {
            ull xa = Xc[2 * (bcol + b) + 0];
            ull xb = Xc[2 * (bcol + b) + 1];
            #pragma unroll
            for (int i = 0; i < NH; i++) {
                aif[i][b] = fma2(wif0[i], xa, fma2(wif1[i], xb, bif[i]));
                ago[i][b] = fma2(wgo0[i], xa, fma2(wgo1[i], xb, bgo[i]));
            }
        }
        gates_mm<H, NH, NB>(Ws, Hc + HOFF * BT + bcol, j0, aif, ago);
        act_update<NH, NB>(aif, ago, cr, Hn + (HOFF + j0) * BT + bcol);
        if (st) {
            Xn[2 * scol + 0] = pk2(xnv.x, xnv.x);
            Xn[2 * scol + 1] = pk2(xnv.y, xnv.y);
        }
        gbar(g);   // one barrier per step (double-buffered h/x)
        { float* tf = Hc; Hc = Hn; Hn = tf; }
        { ull*  tx = Xc; Xc = Xn; Xn = tx; }
    }
    // T even for all phases -> final h lands in H0 (decoder's read buffer)

    // stage final c for the decoder
    #pragma unroll
    for (int i = 0; i < NH; i++)
        #pragma unroll
        for (int b = 0; b < NB; b++)
            Cs[(HOFF + j0 + i) * BT + bcol + b] = cr[i][b];
}

// ---------------- main fused kernel ----------------
__global__ void __launch_bounds__(TPB, 1)
lstm_fused_kernel(const float* __restrict__ traj,   // [B,20,2]
                  const float* __restrict__ cl,     // [B,100,2]
                  const float* __restrict__ Wih_c, const float* __restrict__ Whh_c,
                  const float* __restrict__ bih_c, const float* __restrict__ bhh_c,
                  const float* __restrict__ Wih_e, const float* __restrict__ Whh_e,
                  const float* __restrict__ bih_e, const float* __restrict__ bhh_e,
                  const float* __restrict__ Wih_d, const float* __restrict__ Whh_d,
                  const float* __restrict__ bih_d, const float* __restrict__ bhh_d,
                  const float* __restrict__ W_emb, const float* __restrict__ b_emb,
                  float* __restrict__ out, int B)
{
    extern __shared__ float S[];
    int tid   = threadIdx.x;
    int bbase = blockIdx.x * BT;
    int g     = tid >> 8;        // group 0/1 (owns batch cols [32g, 32g+32))
    int tid_g = tid & 255;

    float*  H0   = S + HS_OFF;
    float*  Cs   = S + CS_OFF;
    ull*    BpkD = (ull*)(S + BPKD_OFF);
    float2* Wemb = (float2*)(S + WEMB_OFF);
    float2* Bemb = (float2*)(S + BEMB_OFF);

    // zero h buffer 0 (initial states for both phases; H1 is written before read)
    for (int s = tid; s < 6144; s += TPB) H0[s] = 0.0f;

    // stage BOTH phases' weights/biases up front (CTA-wide)
    load_W<32>(S + WS_C_OFF, Whh_c, nullptr, tid);
    load_W<64>(S + WS_E_OFF, Whh_e, nullptr, tid);
    load_bias<32>((ull*)(S + BPKC_OFF), bih_c, bhh_c, tid);
    load_ih<32>((ull*)(S + IPKC_OFF), Wih_c, tid);
    load_bias<64>((ull*)(S + BPKE_OFF), bih_e, bhh_e, tid);
    load_ih<64>((ull*)(S + IPKE_OFF), Wih_e, tid);
    __syncthreads();

    // anti-phase schedule: g0 cent->enc, g1 enc->cent (structural MUFU/FMA overlap)
    if (g == 0) {
        lstm_phase<32, 2, 2, 64, 100>(S, cl,   200, B, bbase, g, tid_g, WS_C_OFF, BPKC_OFF, IPKC_OFF);
        lstm_phase<64, 2, 4,  0,  20>(S, traj,  40, B, bbase, g, tid_g, WS_E_OFF, BPKE_OFF, IPKE_OFF);
    } else {
        lstm_phase<64, 2, 4,  0,  20>(S, traj,  40, B, bbase, g, tid_g, WS_E_OFF, BPKE_OFF, IPKE_OFF);
        lstm_phase<32, 2, 2, 64, 100>(S, cl,   200, B, bbase, g, tid_g, WS_C_OFF, BPKC_OFF, IPKC_OFF);
    }
    __syncthreads();

    // ---- decoder (H=96), x == h so Wih+Whh fold into one matrix ----
    {
        constexpr int NH = 3, NB = 4, BG = GBT / NB;   // 32 hidden groups x 8 batch groups
        int hg = tid_g / BG, bg = tid_g % BG;
        int j0 = hg * NH, bcol = g * GBT + bg * NB;

        // read c BEFORE load_W<96> clobbers the aliased Cs region
        float cr[NH][NB];
        #pragma unroll
        for (int i = 0; i < NH; i++)
            #pragma unroll
            for (int b = 0; b < NB; b++)
                cr[i][b] = Cs[(j0 + i) * BT + bcol + b];
        __syncthreads();

        load_W<96>(S + WS_D_OFF, Whh_d, Wih_d, tid);
        load_bias<96>(BpkD, bih_d, bhh_d, tid);
        for (int k = tid; k < 96; k += TPB) Wemb[k] = make_float2(W_emb[k], W_emb[96 + k]);
        if (tid == 0) *Bemb = make_float2(b_emb[0], b_emb[1]);
        __syncthreads();
        if (g) __nanosleep(900);   // half-step skew -> groups' MUFU/fma interleave

        const float* Ws = S + WS_D_OFF;
        ull bif[NH], bgo[NH];
        #pragma unroll
        for (int i = 0; i < NH; i++) {
            bif[i] = BpkD[(j0 + i) * 2 + 0];
            bgo[i] = BpkD[(j0 + i) * 2 + 1];
        }

        float* Hc = S + HS_OFF;          // h0 = concat(enc, cent) in buffer 0
        float* Hn = S + HS_OFF + 6144;

        bool projer = (tid_g < GBT);
        int  pcol   = g * GBT + tid_g;   // projected batch col (tid_g<32)
        int  pb     = bbase + pcol;

        for (int t = 0; t < 30; t++) {
            ull aif[NH][NB], ago[NH][NB];
            #pragma unroll
            for (int i = 0; i < NH; i++)
                #pragma unroll
                for (int b = 0; b < NB; b++) { aif[i][b] = bif[i]; ago[i][b] = bgo[i]; }

            gates_mm<96, NH, NB>(Ws, Hc + bcol, j0, aif, ago);
            act_update<NH, NB>(aif, ago, cr, Hn + j0 * BT + bcol);
            gbar(g);                      // group's new h visible

            // projection: pos = h_new @ W_emb^T + b_emb (32 threads per group;
            // reads Hn only; next step's writes go to Hc -> no conflict)
            if (projer) {
                float2 acc = *Bemb;
                #pragma unroll 8
                for (int k = 0; k < 96; k++) {
                    float  h = Hn[k * BT + pcol];
                    float2 w = Wemb[k];
                    acc.x = fmaf(h, w.x, acc.x);
                    acc.y = fmaf(h, w.y, acc.y);
                }
                if (pb < B) *(float2*)&out[(size_t)(pb * 30 + t) * 2] = acc;
            }
            { float* tf = Hc; Hc = Hn; Hn = tf; }
        }
    }
}

extern "C" void kernel_launch(void* const* d_in, const int* in_sizes, int n_in,
                              void* d_out, int out_size)
{
    const float* traj  = (const float*)d_in[0];
    const float* cl    = (const float*)d_in[1];
    const float* Wih_c = (const float*)d_in[2];
    const float* Whh_c = (const float*)d_in[3];
    const float* bih_c = (const float*)d_in[4];
    const float* bhh_c = (const float*)d_in[5];
    const float* Wih_e = (const float*)d_in[6];
    const float* Whh_e = (const float*)d_in[7];
    const float* bih_e = (const float*)d_in[8];
    const float* bhh_e = (const float*)d_in[9];
    const float* Wih_d = (const float*)d_in[10];
    const float* Whh_d = (const float*)d_in[11];
    const float* bih_d = (const float*)d_in[12];
    const float* bhh_d = (const float*)d_in[13];
    const float* W_emb = (const float*)d_in[14];
    const float* b_emb = (const float*)d_in[15];

    int B = in_sizes[0] / 40;
    int grid = (B + BT - 1) / BT;

    cudaFuncSetAttribute(lstm_fused_kernel,
                         cudaFuncAttributeMaxDynamicSharedMemorySize, SMEM_BYTES);
    lstm_fused_kernel<<<grid, TPB, SMEM_BYTES>>>(
        traj, cl, Wih_c, Whh_c, bih_c, bhh_c,
        Wih_e, Whh_e, bih_e, bhh_e,
        Wih_d, Whh_d, bih_d, bhh_d,
        W_emb, b_emb, (float*)d_out, B);
}

// round 7
// speedup vs baseline: 1.1136x; 1.1136x over previous
#include <cuda_runtime.h>

// Fused 3-phase LSTM (cent H=32 x100, enc H=64 x20, dec H=96 x30).
// R6 = R5 (2 independent 256-thread groups, group-local named barriers,
// anti-phase phase order, double-buffered h/x, 1 barrier/step) with ONE
// change: all activations via HW tanh.approx (MUFU.TANH) -> 5 MUFU/cell
// instead of 10, halving the serialized MUFU burst regardless of how the
// groups phase-lock.

#define TPB  512
#define BT   64
#define GBT  32      // batch columns per group

typedef unsigned long long ull;

// ---------------- packed f32x2 helpers ----------------
__device__ __forceinline__ ull pk2(float lo, float hi) {
    ull r; asm("mov.b64 %0, {%1, %2};" : "=l"(r) : "f"(lo), "f"(hi)); return r;
}
__device__ __forceinline__ ull dup2(float x) {
    ull r; asm("mov.b64 %0, {%1, %1};" : "=l"(r) : "f"(x)); return r;
}
__device__ __forceinline__ ull fma2(ull a, ull b, ull c) {
    ull d; asm("fma.rn.f32x2 %0, %1, %2, %3;" : "=l"(d) : "l"(a), "l"(b), "l"(c)); return d;
}
__device__ __forceinline__ float2 upk(ull a) {
    float lo, hi; asm("mov.b64 {%0, %1}, %2;" : "=f"(lo), "=f"(hi) : "l"(a));
    return make_float2(lo, hi);
}

// ---------------- activations via HW tanh (1 MUFU each) ----------------
__device__ __forceinline__ float tanh_(float x){
    float r; asm("tanh.approx.f32 %0, %1;" : "=f"(r) : "f"(x)); return r;
}
__device__ __forceinline__ float sigm(float x){
    return fmaf(0.5f, tanh_(0.5f * x), 0.5f);
}

// ---------------- group-local named barrier (256 threads) ----------------
__device__ __forceinline__ void gbar(int g) {
    asm volatile("bar.sync %0, %1;" :: "r"(g + 1), "r"(256) : "memory");
}

// ---------------- SMEM layout (float offsets) ----------------
#define WS_D_OFF  0        // decoder weights [0,36864)
#define WS_C_OFF  0        // cent weights   [0,4096)
#define WS_E_OFF  4096     // enc weights    [4096,20480)
#define CS_OFF    20480    // c staging [96][64] = 6144 -> [20480,26624)
#define HS_OFF    36864    // h state: 2 buffers x [96][64] = 2*6144
#define XS_OFF    49152    // dup'd x: 2 buffers x 128 ull = 512 floats
#define BPKC_OFF  49664    // cent bias:  64 ull
#define IPKC_OFF  49792    // cent Wih:  128 ull
#define BPKE_OFF  50048    // enc bias:  128 ull
#define IPKE_OFF  50304    // enc Wih:   256 ull
#define BPKD_OFF  50816    // dec bias:  192 ull
#define WEMB_OFF  51200    // 96 float2
#define BEMB_OFF  51392
#define SMEM_FLOATS 51396
#define SMEM_BYTES  (SMEM_FLOATS * 4)

// ---------------- weight/bias staging (CTA-wide) ----------------
template<int H>
__device__ __forceinline__ void load_W(float* __restrict__ Ws,
                                       const float* __restrict__ Whh,
                                       const float* __restrict__ Wih, int tid)
{
    constexpr int total = 4 * H * H;
    for (int s = tid; s < total; s += TPB) {
        int row = s / H;
        int k   = s - row * H;
        int g   = row / H;
        int j   = row - g * H;
        float v = Whh[s];
        if (Wih) v += Wih[s];
        Ws[k * (4 * H) + j * 4 + g] = v;
    }
}

template<int H>
__device__ __forceinline__ void load_bias(ull* __restrict__ Bpk,
                                          const float* __restrict__ bih,
                                          const float* __restrict__ bhh, int tid)
{
    for (int j = tid; j < H; j += TPB) {
        Bpk[j * 2 + 0] = pk2(bih[j] + bhh[j],             bih[H + j] + bhh[H + j]);
        Bpk[j * 2 + 1] = pk2(bih[2*H + j] + bhh[2*H + j], bih[3*H + j] + bhh[3*H + j]);
    }
}

template<int H>
__device__ __forceinline__ void load_ih(ull* __restrict__ Ipk,
                                        const float* __restrict__ Wih, int tid)
{
    for (int t = tid; t < 2 * H; t += TPB) {
        int j = t >> 1, inp = t & 1;
        Ipk[(j * 2 + inp) * 2 + 0] = pk2(Wih[(0*H + j) * 2 + inp], Wih[(1*H + j) * 2 + inp]);
        Ipk[(j * 2 + inp) * 2 + 1] = pk2(Wih[(2*H + j) * 2 + inp], Wih[(3*H + j) * 2 + inp]);
    }
}

// ---------------- gate matmul: gates += h @ W^T ----------------
template<int H, int NH, int NB>
__device__ __forceinline__ void gates_mm(const float* __restrict__ Ws,
                                         const float* __restrict__ hbase, // Hc+HOFF*BT+bcol
                                         int j0,
                                         ull (&aif)[NH][NB], ull (&ago)[NH][NB])
{
    const float* wb = Ws + j0 * 4;
    #pragma unroll 4
    for (int k = 0; k < H; k++) {
        ull hp[NB];
        if constexpr (NB == 4) {
            float4 hv = *(const float4*)(hbase + k * BT);
            hp[0] = dup2(hv.x); hp[1] = dup2(hv.y); hp[2] = dup2(hv.z); hp[3] = dup2(hv.w);
        } else {
            float2 hv = *(const float2*)(hbase + k * BT);
            hp[0] = dup2(hv.x); hp[1] = dup2(hv.y);
        }
        #pragma unroll
        for (int i = 0; i < NH; i++) {
            ulonglong2 w = *(const ulonglong2*)(wb + k * (4 * H) + i * 4);
            #pragma unroll
            for (int b = 0; b < NB; b++) {
                aif[i][b] = fma2(w.x, hp[b], aif[i][b]);
                ago[i][b] = fma2(w.y, hp[b], ago[i][b]);
            }
        }
    }
}

// ---------------- activations + h store ----------------
template<int NH, int NB>
__device__ __forceinline__ void act_update(ull (&aif)[NH][NB], ull (&ago)[NH][NB],
                                           float (&cr)[NH][NB],
                                           float* __restrict__ Hw) // Hn+(HOFF+j0)*BT+bcol
{
    #pragma unroll
    for (int i = 0; i < NH; i++) {
        float hn[NB];
        #pragma unroll
        for (int b = 0; b < NB; b++) {
            float2 sif = upk(aif[i][b]);
            float2 sgo = upk(ago[i][b]);
            float ig = sigm(sif.x);
            float fg = sigm(sif.y);
            float gg = tanh_(sgo.x);
            float og = sigm(sgo.y);
            float cn = fmaf(fg, cr[i][b], ig * gg);
            cr[i][b] = cn;
            hn[b] = og * tanh_(cn);
        }
        if constexpr (NB == 4)
            *(float4*)(Hw + i * BT) = make_float4(hn[0], hn[1], hn[2], hn[3]);
        else
            *(float2*)(Hw + i * BT) = make_float2(hn[0], hn[1]);
    }
}

// ---------------- one input-driven LSTM phase, group-local ----------------
template<int H, int NH, int NB, int HOFF, int T>
__device__ __forceinline__ void lstm_phase(float* __restrict__ S,
                                           const float* __restrict__ xsrc, int xstride,
                                           int B, int bbase, int g, int tid_g,
                                           int wsOff, int bpkOff, int ipkOff)
{
    constexpr int BG = GBT / NB;
    static_assert((H / NH) * BG == 256, "group thread map");
    int hg = tid_g / BG, bg = tid_g % BG;
    int j0 = hg * NH, bcol = g * GBT + bg * NB;

    float* Ws = S + wsOff;
    float* Cs = S + CS_OFF;
    float* H0 = S + HS_OFF;  float* H1 = H0 + 6144;
    ull*   X0 = (ull*)(S + XS_OFF); ull* X1 = X0 + 128;
    ull*   Bpk = (ull*)(S + bpkOff);
    ull*   Ipk = (ull*)(S + ipkOff);

    float cr[NH][NB];
    #pragma unroll
    for (int i = 0; i < NH; i++)
        #pragma unroll
        for (int b = 0; b < NB; b++) cr[i][b] = 0.0f;

    ull bif[NH], bgo[NH], wif0[NH], wif1[NH], wgo0[NH], wgo1[NH];
    #pragma unroll
    for (int i = 0; i < NH; i++) {
        bif[i]  = Bpk[(j0 + i) * 2 + 0];
        bgo[i]  = Bpk[(j0 + i) * 2 + 1];
        wif0[i] = Ipk[((j0 + i) * 2 + 0) * 2 + 0];
        wgo0[i] = Ipk[((j0 + i) * 2 + 0) * 2 + 1];
        wif1[i] = Ipk[((j0 + i) * 2 + 1) * 2 + 0];
        wgo1[i] = Ipk[((j0 + i) * 2 + 1) * 2 + 1];
    }

    // initial x stage (group-local; 32 stager threads)
    bool stager = (tid_g < GBT);
    int  scol = g * GBT + tid_g;
    int  bb = bbase + scol; if (bb >= B) bb = B - 1;
    if (stager) {
        float2 x = *(const float2*)&xsrc[(size_t)bb * xstride];
        X0[2 * scol + 0] = pk2(x.x, x.x);
        X0[2 * scol + 1] = pk2(x.y, x.y);
    }
    gbar(g);

    float* Hc = H0; float* Hn = H1;
    ull*   Xc = X0; ull*   Xn = X1;

    for (int t = 0; t < T; t++) {
        float2 xnv;
        bool st = stager && (t + 1 < T);
        if (st)   // prefetch next x early; LDG hides under gates_mm
            xnv = *(const float2*)&xsrc[(size_t)bb * xstride + (size_t)(t + 1) * 2];

        ull aif[NH][NB], ago[NH][NB];
        #pragma unroll
        for (int b = 0; b < NB; b++) {
            ull xa = Xc[2 * (bcol + b) + 0];
            ull xb = Xc[2 * (bcol + b) + 1];
            #pragma unroll
            for (int i = 0; i < NH; i++) {
                aif[i][b] = fma2(wif0[i], xa, fma2(wif1[i], xb, bif[i]));
                ago[i][b] = fma2(wgo0[i], xa, fma2(wgo1[i], xb, bgo[i]));
            }
        }
        gates_mm<H, NH, NB>(Ws, Hc + HOFF * BT + bcol, j0, aif, ago);
        act_update<NH, NB>(aif, ago, cr, Hn + (HOFF + j0) * BT + bcol);
        if (st) {
            Xn[2 * scol + 0] = pk2(xnv.x, xnv.x);
            Xn[2 * scol + 1] = pk2(xnv.y, xnv.y);
        }
        gbar(g);   // one barrier per step (double-buffered h/x)
        { float* tf = Hc; Hc = Hn; Hn = tf; }
        { ull*  tx = Xc; Xc = Xn; Xn = tx; }
    }
    // T even for all phases -> final h lands in H0 (decoder's read buffer)

    // stage final c for the decoder
    #pragma unroll
    for (int i = 0; i < NH; i++)
        #pragma unroll
        for (int b = 0; b < NB; b++)
            Cs[(HOFF + j0 + i) * BT + bcol + b] = cr[i][b];
}

// ---------------- main fused kernel ----------------
__global__ void __launch_bounds__(TPB, 1)
lstm_fused_kernel(const float* __restrict__ traj,   // [B,20,2]
                  const float* __restrict__ cl,     // [B,100,2]
                  const float* __restrict__ Wih_c, const float* __restrict__ Whh_c,
                  const float* __restrict__ bih_c, const float* __restrict__ bhh_c,
                  const float* __restrict__ Wih_e, const float* __restrict__ Whh_e,
                  const float* __restrict__ bih_e, const float* __restrict__ bhh_e,
                  const float* __restrict__ Wih_d, const float* __restrict__ Whh_d,
                  const float* __restrict__ bih_d, const float* __restrict__ bhh_d,
                  const float* __restrict__ W_emb, const float* __restrict__ b_emb,
                  float* __restrict__ out, int B)
{
    extern __shared__ float S[];
    int tid   = threadIdx.x;
    int bbase = blockIdx.x * BT;
    int g     = tid >> 8;        // group 0/1 (owns batch cols [32g, 32g+32))
    int tid_g = tid & 255;

    float*  H0   = S + HS_OFF;
    float*  Cs   = S + CS_OFF;
    ull*    BpkD = (ull*)(S + BPKD_OFF);
    float2* Wemb = (float2*)(S + WEMB_OFF);
    float2* Bemb = (float2*)(S + BEMB_OFF);

    // zero h buffer 0 (initial states for both phases; H1 is written before read)
    for (int s = tid; s < 6144; s += TPB) H0[s] = 0.0f;

    // stage BOTH phases' weights/biases up front (CTA-wide)
    load_W<32>(S + WS_C_OFF, Whh_c, nullptr, tid);
    load_W<64>(S + WS_E_OFF, Whh_e, nullptr, tid);
    load_bias<32>((ull*)(S + BPKC_OFF), bih_c, bhh_c, tid);
    load_ih<32>((ull*)(S + IPKC_OFF), Wih_c, tid);
    load_bias<64>((ull*)(S + BPKE_OFF), bih_e, bhh_e, tid);
    load_ih<64>((ull*)(S + IPKE_OFF), Wih_e, tid);
    __syncthreads();

    // anti-phase schedule: g0 cent->enc, g1 enc->cent (structural MUFU/FMA overlap)
    if (g == 0) {
        lstm_phase<32, 2, 2, 64, 100>(S, cl,   200, B, bbase, g, tid_g, WS_C_OFF, BPKC_OFF, IPKC_OFF);
        lstm_phase<64, 2, 4,  0,  20>(S, traj,  40, B, bbase, g, tid_g, WS_E_OFF, BPKE_OFF, IPKE_OFF);
    } else {
        lstm_phase<64, 2, 4,  0,  20>(S, traj,  40, B, bbase, g, tid_g, WS_E_OFF, BPKE_OFF, IPKE_OFF);
        lstm_phase<32, 2, 2, 64, 100>(S, cl,   200, B, bbase, g, tid_g, WS_C_OFF, BPKC_OFF, IPKC_OFF);
    }
    __syncthreads();

    // ---- decoder (H=96), x == h so Wih+Whh fold into one matrix ----
    {
        constexpr int NH = 3, NB = 4, BG = GBT / NB;   // 32 hidden groups x 8 batch groups
        int hg = tid_g / BG, bg = tid_g % BG;
        int j0 = hg * NH, bcol = g * GBT + bg * NB;

        // read c BEFORE load_W<96> clobbers the aliased Cs region
        float cr[NH][NB];
        #pragma unroll
        for (int i = 0; i < NH; i++)
            #pragma unroll
            for (int b = 0; b < NB; b++)
                cr[i][b] = Cs[(j0 + i) * BT + bcol + b];
        __syncthreads();

        load_W<96>(S + WS_D_OFF, Whh_d, Wih_d, tid);
        load_bias<96>(BpkD, bih_d, bhh_d, tid);
        for (int k = tid; k < 96; k += TPB) Wemb[k] = make_float2(W_emb[k], W_emb[96 + k]);
        if (tid == 0) *Bemb = make_float2(b_emb[0], b_emb[1]);
        __syncthreads();
        if (g) __nanosleep(2000);  // ~half-step skew -> bias toward anti-phase lock

        const float* Ws = S + WS_D_OFF;
        ull bif[NH], bgo[NH];
        #pragma unroll
        for (int i = 0; i < NH; i++) {
            bif[i] = BpkD[(j0 + i) * 2 + 0];
            bgo[i] = BpkD[(j0 + i) * 2 + 1];
        }

        float* Hc = S + HS_OFF;          // h0 = concat(enc, cent) in buffer 0
        float* Hn = S + HS_OFF + 6144;

        bool projer = (tid_g < GBT);
        int  pcol   = g * GBT + tid_g;   // projected batch col (tid_g<32)
        int  pb     = bbase + pcol;

        for (int t = 0; t < 30; t++) {
            ull aif[NH][NB], ago[NH][NB];
            #pragma unroll
            for (int i = 0; i < NH; i++)
                #pragma unroll
                for (int b = 0; b < NB; b++) { aif[i][b] = bif[i]; ago[i][b] = bgo[i]; }

            gates_mm<96, NH, NB>(Ws, Hc + bcol, j0, aif, ago);
            act_update<NH, NB>(aif, ago, cr, Hn + j0 * BT + bcol);
            gbar(g);                      // group's new h visible

            // projection: pos = h_new @ W_emb^T + b_emb (32 threads per group;
            // reads Hn only; next step's writes go to Hc -> no conflict)
            if (projer) {
                float2 acc = *Bemb;
                #pragma unroll 8
                for (int k = 0; k < 96; k++) {
                    float  h = Hn[k * BT + pcol];
                    float2 w = Wemb[k];
                    acc.x = fmaf(h, w.x, acc.x);
                    acc.y = fmaf(h, w.y, acc.y);
                }
                if (pb < B) *(float2*)&out[(size_t)(pb * 30 + t) * 2] = acc;
            }
            { float* tf = Hc; Hc = Hn; Hn = tf; }
        }
    }
}

extern "C" void kernel_launch(void* const* d_in, const int* in_sizes, int n_in,
                              void* d_out, int out_size)
{
    const float* traj  = (const float*)d_in[0];
    const float* cl    = (const float*)d_in[1];
    const float* Wih_c = (const float*)d_in[2];
    const float* Whh_c = (const float*)d_in[3];
    const float* bih_c = (const float*)d_in[4];
    const float* bhh_c = (const float*)d_in[5];
    const float* Wih_e = (const float*)d_in[6];
    const float* Whh_e = (const float*)d_in[7];
    const float* bih_e = (const float*)d_in[8];
    const float* bhh_e = (const float*)d_in[9];
    const float* Wih_d = (const float*)d_in[10];
    const float* Whh_d = (const float*)d_in[11];
    const float* bih_d = (const float*)d_in[12];
    const float* bhh_d = (const float*)d_in[13];
    const float* W_emb = (const float*)d_in[14];
    const float* b_emb = (const float*)d_in[15];

    int B = in_sizes[0] / 40;
    int grid = (B + BT - 1) / BT;

    cudaFuncSetAttribute(lstm_fused_kernel,
                         cudaFuncAttributeMaxDynamicSharedMemorySize, SMEM_BYTES);
    lstm_fused_kernel<<<grid, TPB, SMEM_BYTES>>>(
        traj, cl, Wih_c, Whh_c, bih_c, bhh_c,
        Wih_e, Whh_e, bih_e, bhh_e,
        Wih_d, Whh_d, bih_d, bhh_d,
        W_emb, b_emb, (float*)d_out, B);
}